// round 7
// baseline (speedup 1.0000x reference)
#include <cuda_runtime.h>

// ---------------------------------------------------------------------------
// pLoss via mma.sync (bf16 HMMA): pot = S f^T ; P = softmax_s ; pMargin = P^T S.
// No shift: S binary => |pot| <= ~26, exp(pot) in fp32 range; uniform per-row
// shifts don't change relative accuracy.
// f is an exact hi/lo bf16 split (pot exact up to fp32 accumulation).
// w is rn-rounded bf16; Z sums the SAME rounded values (errors cancel in M/Z).
// S is fetched as fp32 via a 3-stage cp.async pipeline and converted to a bf16
// SMEM tile one chunk ahead of the GEMMs (no separate conversion kernel).
// 296 CTAs (74 splits x 4 batch-tiles) = 2 CTAs/SM, one wave.
// finalize does pMargin + BCE + final loss reduce (last-block). 2 launches.
// ---------------------------------------------------------------------------

#define NB       512
#define NL       64
#define SPLITS   74
#define CPS      7           // chunks per split (73*7 + 1 = 512)
#define TOTCH    512

// SMEM layout (bytes):
//   fp32 tile buffers: 3 x (64 rows x 272B) = 52224   at 0
//   bf16 tile buffers: 2 x (64 rows x 144B) = 18432   at 52224
// f staging (pre-loop only) overlaps fp32 buffers: 128 x 272 = 34816.
#define F32OF(b) ((b) * 17408)
#define BFOF(b)  (52224 + (b) * 9216)
#define SMEM_BYTES 70656

__device__ float g_Zpart[SPLITS * NB];
__device__ float g_Mpart[SPLITS * NB * NL];
__device__ float g_lpart[256];
__device__ unsigned g_cnt;                     // zero-init; self-resetting

// ---------------- helpers ----------------
__device__ __forceinline__ unsigned smem_u32(const void* p) {
    unsigned a;
    asm("{ .reg .u64 t; cvta.to.shared.u64 t, %1; cvt.u32.u64 %0, t; }"
        : "=r"(a) : "l"(p));
    return a;
}
__device__ __forceinline__ void ldsm4(unsigned* r, unsigned addr) {
    asm volatile("ldmatrix.sync.aligned.m8n8.x4.shared.b16 {%0,%1,%2,%3}, [%4];"
                 : "=r"(r[0]), "=r"(r[1]), "=r"(r[2]), "=r"(r[3]) : "r"(addr));
}
__device__ __forceinline__ void ldsm4t(unsigned* r, unsigned addr) {
    asm volatile("ldmatrix.sync.aligned.m8n8.x4.trans.shared.b16 {%0,%1,%2,%3}, [%4];"
                 : "=r"(r[0]), "=r"(r[1]), "=r"(r[2]), "=r"(r[3]) : "r"(addr));
}
__device__ __forceinline__ void mma16816(float* d, const unsigned* a,
                                         unsigned b0, unsigned b1) {
    asm volatile(
        "mma.sync.aligned.m16n8k16.row.col.f32.bf16.bf16.f32 "
        "{%0,%1,%2,%3}, {%4,%5,%6,%7}, {%8,%9}, {%0,%1,%2,%3};"
        : "+f"(d[0]), "+f"(d[1]), "+f"(d[2]), "+f"(d[3])
        : "r"(a[0]), "r"(a[1]), "r"(a[2]), "r"(a[3]), "r"(b0), "r"(b1));
}
__device__ __forceinline__ unsigned packhi(float a, float b) {   // exact trunc
    return __byte_perm(__float_as_uint(a), __float_as_uint(b), 0x7632);
}
__device__ __forceinline__ unsigned packlo(float a, float b) {   // exact residual
    float la = a - __uint_as_float(__float_as_uint(a) & 0xFFFF0000u);
    float lb = b - __uint_as_float(__float_as_uint(b) & 0xFFFF0000u);
    unsigned r;
    asm("cvt.rn.bf16x2.f32 %0, %1, %2;" : "=r"(r) : "f"(lb), "f"(la));
    return r;
}
__device__ __forceinline__ unsigned packrn(float a, float b) {   // rn round
    unsigned r;
    asm("cvt.rn.bf16x2.f32 %0, %1, %2;" : "=r"(r) : "f"(b), "f"(a));
    return r;
}
__device__ __forceinline__ void cpasync16(unsigned saddr, const void* g) {
    asm volatile("cp.async.cg.shared.global [%0], [%1], 16;"
                 :: "r"(saddr), "l"(g));
}
__device__ __forceinline__ void cp_commit() {
    asm volatile("cp.async.commit_group;" ::: "memory");
}
__device__ __forceinline__ void cp_wait2() {
    asm volatile("cp.async.wait_group 2;" ::: "memory");
}

// ---------------- main kernel ----------------
__global__ __launch_bounds__(256, 2)
void main_kernel(const float* __restrict__ f, const float* __restrict__ Sg) {
    extern __shared__ char smem[];
    const unsigned sb = smem_u32(smem);

    const int tid  = threadIdx.x;
    const int wid  = tid >> 5;
    const int lane = tid & 31;
    const int b0   = blockIdx.y * 128;
    const int c0   = blockIdx.x * CPS;
    const int c1   = min(c0 + CPS, TOTCH);

    // ---- stage f hi/lo split into SMEM (overlaps fp32 buffers; pre-loop) ----
    {
        const int b = tid >> 1, half = tid & 1;
        const float* fr = f + (size_t)(b0 + b) * NL + half * 32;
        char* frow = smem + b * 272;
        #pragma unroll
        for (int j = 0; j < 8; j++) {
            float4 v = *(const float4*)(fr + 4 * j);
            int ch = half * 32 + 4 * j;
            *(uint2*)(frow + ch * 2) =
                make_uint2(packhi(v.x, v.y), packhi(v.z, v.w));
            *(uint2*)(frow + (64 + ch) * 2) =
                make_uint2(packlo(v.x, v.y), packlo(v.z, v.w));
        }
    }
    __syncthreads();

    // ---- A fragments (f hi: q=0..3, f lo: q=4..7), persistent ----
    unsigned fa[8][4];
    const int r0 = wid * 16;
    {
        const unsigned laneA = (lane % 16) * 272 + (lane >> 4) * 16;
        #pragma unroll
        for (int q = 0; q < 8; q++)
            ldsm4(fa[q], sb + r0 * 272 + q * 32 + laneA);
    }
    __syncthreads();   // staging dead; fp32 buffers may now be written

    // ---- cp.async pipeline (fp32 tiles), 4 quads/thread/chunk ----
    // quad q (0..1023): row=q>>4, colq=q&15 -> smem row*272 + colq*16,
    //                                gmem  c*16384 + row*256 + colq*16.
    unsigned sqo[4]; size_t gqo[4];
    #pragma unroll
    for (int k = 0; k < 4; k++) {
        int q = tid + k * 256;
        sqo[k] = (unsigned)((q >> 4) * 272 + (q & 15) * 16);
        gqo[k] = (size_t)(q >> 4) * 256 + (q & 15) * 16;
    }
    #define ISSUE(c, slot)                                                    \
        do {                                                                  \
            const char* gb_ = (const char*)Sg + (size_t)(c) * 16384;          \
            const unsigned sb_ = sb + F32OF(slot);                            \
            cpasync16(sb_ + sqo[0], gb_ + gqo[0]);                            \
            cpasync16(sb_ + sqo[1], gb_ + gqo[1]);                            \
            cpasync16(sb_ + sqo[2], gb_ + gqo[2]);                            \
            cpasync16(sb_ + sqo[3], gb_ + gqo[3]);                            \
        } while (0)

    // convert chunk cc from fp32 slot -> bf16 buffer (cc&1)
    const unsigned csrow  = (unsigned)(tid >> 2);
    const unsigned cibase = (unsigned)((tid & 3) << 4);
    #define CONVERT(cc, slot)                                                 \
        do {                                                                  \
            const char* sp_ = smem + F32OF(slot) + csrow * 272 + cibase * 4;  \
            float4 a0 = *(const float4*)(sp_ + 0);                            \
            float4 a1 = *(const float4*)(sp_ + 16);                           \
            float4 a2 = *(const float4*)(sp_ + 32);                           \
            float4 a3 = *(const float4*)(sp_ + 48);                           \
            char* dp_ = smem + BFOF((cc) & 1) + csrow * 144 + cibase * 2;     \
            *(uint4*)(dp_ + 0)  = make_uint4(packrn(a0.x, a0.y),              \
                                             packrn(a0.z, a0.w),              \
                                             packrn(a1.x, a1.y),              \
                                             packrn(a1.z, a1.w));             \
            *(uint4*)(dp_ + 16) = make_uint4(packrn(a2.x, a2.y),              \
                                             packrn(a2.z, a2.w),              \
                                             packrn(a3.x, a3.y),              \
                                             packrn(a3.z, a3.w));             \
        } while (0)

    ISSUE(c0, 0); cp_commit();
    if (c0 + 1 < c1) ISSUE(c0 + 1, 1);
    cp_commit();
    if (c0 + 2 < c1) ISSUE(c0 + 2, 2);
    cp_commit();
    cp_wait2();          // chunk c0 arrived
    __syncthreads();
    CONVERT(c0, 0);

    // ---- chunk loop ----
    float macc[8][4];
    #pragma unroll
    for (int j = 0; j < 8; j++)
        #pragma unroll
        for (int k = 0; k < 4; k++) macc[j][k] = 0.f;
    float zacc0 = 0.f, zacc1 = 0.f;

    const unsigned laneB = (lane & 7) * 144 + (lane >> 3) * 16;  // GEMM1
    const unsigned laneT = lane * 144;                           // GEMM2 (trans)

    for (int c = c0; c < c1; c++) {
        const int idx = c - c0;

        __syncthreads();   // convert(c) visible; GEMM(c-1) reads done

        if (c + 3 < c1) ISSUE(c + 3, idx % 3);   // slot of chunk c (converted)
        cp_commit();
        if (c + 1 < c1) {
            cp_wait2();                          // chunk c+1 arrived
            CONVERT(c + 1, (idx + 1) % 3);
        }

        const unsigned bfb = sb + BFOF(c & 1);
        const unsigned ssb = bfb + laneB;
        const unsigned sst = bfb + laneT;

        // ---- GEMM1: scores[16 rows][64 s] = f . S^T ----
        float d[8][4];
        #pragma unroll
        for (int j = 0; j < 8; j++)
            #pragma unroll
            for (int k = 0; k < 4; k++) d[j][k] = 0.f;

        #pragma unroll
        for (int j = 0; j < 8; j++) {
            #pragma unroll
            for (int qp = 0; qp < 2; qp++) {
                unsigned bfr[4];
                ldsm4(bfr, ssb + j * 1152 + qp * 64);
                mma16816(d[j], fa[2 * qp],     bfr[0], bfr[1]);
                mma16816(d[j], fa[2 * qp + 1], bfr[2], bfr[3]);
                mma16816(d[j], fa[4 + 2 * qp],     bfr[0], bfr[1]);
                mma16816(d[j], fa[4 + 2 * qp + 1], bfr[2], bfr[3]);
            }
        }

        // ---- epilogue: w = rn_bf16(exp(pot)); Z from rounded values ----
        unsigned wh[4][4];
        #pragma unroll
        for (int j = 0; j < 8; j++) {
            float e0 = __expf(d[j][0]);
            float e1 = __expf(d[j][1]);
            float e2 = __expf(d[j][2]);
            float e3 = __expf(d[j][3]);
            const int q = j >> 1, bx = (j & 1) * 2;
            unsigned p01 = packrn(e0, e1);
            unsigned p23 = packrn(e2, e3);
            wh[q][bx]     = p01;
            wh[q][bx + 1] = p23;
            zacc0 += __uint_as_float(p01 << 16) +
                     __uint_as_float(p01 & 0xFFFF0000u);
            zacc1 += __uint_as_float(p23 << 16) +
                     __uint_as_float(p23 & 0xFFFF0000u);
        }

        // ---- GEMM2: M[16 rows][64 i] += w . S (B via ldmatrix.trans) ----
        #pragma unroll
        for (int j = 0; j < 8; j++) {
            #pragma unroll
            for (int qp = 0; qp < 2; qp++) {
                unsigned bfr[4];
                ldsm4t(bfr, sst + qp * 4608 + j * 16);
                mma16816(macc[j], wh[2 * qp],     bfr[0], bfr[1]);
                mma16816(macc[j], wh[2 * qp + 1], bfr[2], bfr[3]);
            }
        }
    }
    #undef ISSUE
    #undef CONVERT

    // ---- Z partials (quad reduce) ----
    zacc0 += __shfl_xor_sync(0xFFFFFFFFu, zacc0, 1);
    zacc0 += __shfl_xor_sync(0xFFFFFFFFu, zacc0, 2);
    zacc1 += __shfl_xor_sync(0xFFFFFFFFu, zacc1, 1);
    zacc1 += __shfl_xor_sync(0xFFFFFFFFu, zacc1, 2);
    if ((lane & 3) == 0) {
        const int r = b0 + r0 + (lane >> 2);
        g_Zpart[blockIdx.x * NB + r]     = zacc0;
        g_Zpart[blockIdx.x * NB + r + 8] = zacc1;
    }

    // ---- M partials writeback ----
    {
        float* mb = g_Mpart + (size_t)blockIdx.x * (NB * NL)
                  + (size_t)(b0 + r0 + (lane >> 2)) * NL + (lane & 3) * 2;
        float* mb2 = mb + 8 * NL;
        #pragma unroll
        for (int j = 0; j < 8; j++) {
            *(float2*)(mb  + 8 * j) = make_float2(macc[j][0], macc[j][1]);
            *(float2*)(mb2 + 8 * j) = make_float2(macc[j][2], macc[j][3]);
        }
    }
}

// ------- finalize: splits sum, pMargin, BCE, last-block loss reduce -------
__global__ void finalize_kernel(const float* __restrict__ y,
                                const float* __restrict__ mask,
                                float* __restrict__ out) {
    const int half = threadIdx.x >> 7;
    const int el   = threadIdx.x & 127;
    const int idx  = blockIdx.x * 128 + el;

    float m = 0.f;
    const int kbase = half * 37;
    #pragma unroll
    for (int k = 0; k < 37; k++)
        m += g_Mpart[(size_t)(kbase + k) * (NB * NL) + idx];

    __shared__ float buf[128];
    __shared__ float red[256];
    __shared__ float Zsm[2];
    __shared__ int slast;
    if (threadIdx.x < 2) {
        float z = 0.f;
        #pragma unroll
        for (int k = 0; k < SPLITS; k++)
            z += g_Zpart[k * NB + blockIdx.x * 2 + threadIdx.x];
        Zsm[threadIdx.x] = z;
    }
    if (half) buf[el] = m;
    __syncthreads();

    float bce = 0.f;
    if (!half) {
        m += buf[el];
        float p = m / Zsm[el >> 6];
        out[1 + idx] = p;
        float yv = y[idx], mv = mask[idx];
        float lp  = fmaxf(logf(p), -100.f);
        float l1p = fmaxf(logf(fmaxf(1.f - p, 0.f)), -100.f);
        bce = -(yv * lp + (1.f - yv) * l1p) * mv;
    }
    red[threadIdx.x] = bce;
    __syncthreads();
    #pragma unroll
    for (int off = 128; off > 0; off >>= 1) {
        if (threadIdx.x < off) red[threadIdx.x] += red[threadIdx.x + off];
        __syncthreads();
    }

    // last-block final reduction (deterministic: fixed-order sum of 256 vals)
    if (threadIdx.x == 0) {
        g_lpart[blockIdx.x] = red[0];
        __threadfence();
        unsigned t = atomicAdd(&g_cnt, 1u);
        slast = (t == gridDim.x - 1) ? 1 : 0;
    }
    __syncthreads();
    if (slast) {
        red[threadIdx.x] = g_lpart[threadIdx.x];
        __syncthreads();
        #pragma unroll
        for (int off = 128; off > 0; off >>= 1) {
            if (threadIdx.x < off) red[threadIdx.x] += red[threadIdx.x + off];
            __syncthreads();
        }
        if (threadIdx.x == 0) {
            out[0] = red[0] * (1.f / NB);
            g_cnt = 0;                       // reset for next graph replay
        }
    }
}

extern "C" void kernel_launch(void* const* d_in, const int* in_sizes, int n_in,
                              void* d_out, int out_size) {
    const float* f    = (const float*)d_in[0];
    const float* S    = (const float*)d_in[1];
    const float* y    = (const float*)d_in[2];
    const float* mask = (const float*)d_in[3];
    float* out = (float*)d_out;

    cudaFuncSetAttribute(main_kernel, cudaFuncAttributeMaxDynamicSharedMemorySize,
                         SMEM_BYTES);
    dim3 grid(SPLITS, 4);
    main_kernel<<<grid, 256, SMEM_BYTES>>>(f, S);
    finalize_kernel<<<NB * NL / 128, 256>>>(y, mask, out);
}

// round 8
// speedup vs baseline: 1.0067x; 1.0067x over previous
#include <cuda_runtime.h>

// ---------------------------------------------------------------------------
// pLoss via mma.sync (bf16 HMMA): pot = S f^T ; P = softmax_s ; pMargin = P^T S.
// No shift: S binary => |pot| <= ~26, exp(pot) in fp32 range; uniform per-row
// shifts don't change relative accuracy.
// f is an exact hi/lo bf16 split (pot exact up to fp32 accumulation).
// w is rn-rounded bf16; Z sums the SAME rounded values (errors cancel in M/Z).
// S pre-converted to bf16 once; main loop: 3-stage cp.async bf16 tile pipeline.
// 296 CTAs (74 splits x 4 batch-tiles) = 2 CTAs/SM, one wave. Main kernel runs
// at the bf16 HMMA roofline (~10.4us). finalize uses LDG.128 split-sums
// (8 groups x float4) + last-block loss reduction. 3 launches total.
// ---------------------------------------------------------------------------

#define NB       512
#define NL       64
#define SPLITS   74
#define CPS      7           // chunks per split (73*7 + 1 = 512)
#define TOTCH    512

#define SSOF(b)  ((b) * 9216)      // 3 tile buffers, 64 rows x 144B each
#define SMEM_BYTES 34816           // f staging (pre-loop) needs 128*272 = 34816

__device__ unsigned short g_Sbf[32768 * 64];   // bf16 copy of S (4 MB)
__device__ float g_Zpart[SPLITS * NB];
__device__ __align__(16) float g_Mpart[SPLITS * NB * NL];
__device__ float g_lpart[256];
__device__ unsigned g_cnt;                     // zero-init; self-resetting

// ---------------- helpers ----------------
__device__ __forceinline__ unsigned smem_u32(const void* p) {
    unsigned a;
    asm("{ .reg .u64 t; cvta.to.shared.u64 t, %1; cvt.u32.u64 %0, t; }"
        : "=r"(a) : "l"(p));
    return a;
}
__device__ __forceinline__ void ldsm4(unsigned* r, unsigned addr) {
    asm volatile("ldmatrix.sync.aligned.m8n8.x4.shared.b16 {%0,%1,%2,%3}, [%4];"
                 : "=r"(r[0]), "=r"(r[1]), "=r"(r[2]), "=r"(r[3]) : "r"(addr));
}
__device__ __forceinline__ void ldsm4t(unsigned* r, unsigned addr) {
    asm volatile("ldmatrix.sync.aligned.m8n8.x4.trans.shared.b16 {%0,%1,%2,%3}, [%4];"
                 : "=r"(r[0]), "=r"(r[1]), "=r"(r[2]), "=r"(r[3]) : "r"(addr));
}
__device__ __forceinline__ void mma16816(float* d, const unsigned* a,
                                         unsigned b0, unsigned b1) {
    asm volatile(
        "mma.sync.aligned.m16n8k16.row.col.f32.bf16.bf16.f32 "
        "{%0,%1,%2,%3}, {%4,%5,%6,%7}, {%8,%9}, {%0,%1,%2,%3};"
        : "+f"(d[0]), "+f"(d[1]), "+f"(d[2]), "+f"(d[3])
        : "r"(a[0]), "r"(a[1]), "r"(a[2]), "r"(a[3]), "r"(b0), "r"(b1));
}
__device__ __forceinline__ unsigned packhi(float a, float b) {   // exact trunc
    return __byte_perm(__float_as_uint(a), __float_as_uint(b), 0x7632);
}
__device__ __forceinline__ unsigned packlo(float a, float b) {   // exact residual
    float la = a - __uint_as_float(__float_as_uint(a) & 0xFFFF0000u);
    float lb = b - __uint_as_float(__float_as_uint(b) & 0xFFFF0000u);
    unsigned r;
    asm("cvt.rn.bf16x2.f32 %0, %1, %2;" : "=r"(r) : "f"(lb), "f"(la));
    return r;
}
__device__ __forceinline__ unsigned packrn(float a, float b) {   // rn round
    unsigned r;
    asm("cvt.rn.bf16x2.f32 %0, %1, %2;" : "=r"(r) : "f"(b), "f"(a));
    return r;
}
__device__ __forceinline__ void cpasync16(unsigned saddr, const void* g) {
    asm volatile("cp.async.cg.shared.global [%0], [%1], 16;"
                 :: "r"(saddr), "l"(g));
}
__device__ __forceinline__ void cp_commit() {
    asm volatile("cp.async.commit_group;" ::: "memory");
}
__device__ __forceinline__ void cp_wait1() {
    asm volatile("cp.async.wait_group 1;" ::: "memory");
}

// ---------------- S -> bf16 conversion ----------------
__global__ void conv_kernel(const float* __restrict__ S) {
    const int t = blockIdx.x * 256 + threadIdx.x;     // 8 elems each
    float4 a = ((const float4*)S)[2 * t];
    float4 b = ((const float4*)S)[2 * t + 1];
    uint4 o;
    o.x = packrn(a.x, a.y);  o.y = packrn(a.z, a.w);
    o.z = packrn(b.x, b.y);  o.w = packrn(b.z, b.w);
    ((uint4*)g_Sbf)[t] = o;
}

// ---------------- main kernel ----------------
__global__ __launch_bounds__(256, 2)
void main_kernel(const float* __restrict__ f) {
    extern __shared__ char smem[];
    const unsigned sb = smem_u32(smem);

    const int tid  = threadIdx.x;
    const int wid  = tid >> 5;
    const int lane = tid & 31;
    const int b0   = blockIdx.y * 128;
    const int c0   = blockIdx.x * CPS;
    const int c1   = min(c0 + CPS, TOTCH);

    // ---- stage f hi/lo split into SMEM ----
    {
        const int b = tid >> 1, half = tid & 1;
        const float* fr = f + (size_t)(b0 + b) * NL + half * 32;
        char* frow = smem + b * 272;
        #pragma unroll
        for (int j = 0; j < 8; j++) {
            float4 v = *(const float4*)(fr + 4 * j);
            int ch = half * 32 + 4 * j;
            *(uint2*)(frow + ch * 2) =
                make_uint2(packhi(v.x, v.y), packhi(v.z, v.w));
            *(uint2*)(frow + (64 + ch) * 2) =
                make_uint2(packlo(v.x, v.y), packlo(v.z, v.w));
        }
    }
    __syncthreads();

    // ---- A fragments (f hi: q=0..3, f lo: q=4..7), persistent ----
    unsigned fa[8][4];
    const int r0 = wid * 16;
    {
        const unsigned laneA = (lane % 16) * 272 + (lane >> 4) * 16;
        #pragma unroll
        for (int q = 0; q < 8; q++)
            ldsm4(fa[q], sb + r0 * 272 + q * 32 + laneA);
    }
    __syncthreads();   // staging dead; cp.async buffers may now be written

    // ---- cp.async pipeline prologue ----
    const int q0 = tid, q1 = tid + 256;
    const unsigned so0 = (unsigned)((q0 >> 3) * 144 + (q0 & 7) * 16);
    const unsigned so1 = (unsigned)((q1 >> 3) * 144 + (q1 & 7) * 16);

    #define ISSUE(c, buf)                                                   \
        do {                                                                \
            const char* gb_ = (const char*)g_Sbf + (size_t)(c) * 8192;      \
            cpasync16(sb + SSOF(buf) + so0, gb_ + q0 * 16);                 \
            cpasync16(sb + SSOF(buf) + so1, gb_ + q1 * 16);                 \
        } while (0)

    ISSUE(c0, 0); cp_commit();
    if (c0 + 1 < c1) ISSUE(c0 + 1, 1);
    cp_commit();

    // ---- chunk loop ----
    float macc[8][4];
    #pragma unroll
    for (int j = 0; j < 8; j++)
        #pragma unroll
        for (int k = 0; k < 4; k++) macc[j][k] = 0.f;
    float zacc0 = 0.f, zacc1 = 0.f;

    const unsigned laneB = (lane & 7) * 144 + (lane >> 3) * 16;  // GEMM1
    const unsigned laneT = lane * 144;                           // GEMM2 (trans)

    for (int c = c0; c < c1; c++) {
        const int idx = c - c0;
        const int buf = idx % 3;

        cp_wait1();
        __syncthreads();

        if (c + 2 < c1) ISSUE(c + 2, (idx + 2) % 3);
        cp_commit();

        const unsigned ssb = sb + SSOF(buf) + laneB;
        const unsigned sst = sb + SSOF(buf) + laneT;

        // ---- GEMM1: scores[16 rows][64 s] = f . S^T ----
        float d[8][4];
        #pragma unroll
        for (int j = 0; j < 8; j++)
            #pragma unroll
            for (int k = 0; k < 4; k++) d[j][k] = 0.f;

        #pragma unroll
        for (int j = 0; j < 8; j++) {
            #pragma unroll
            for (int qp = 0; qp < 2; qp++) {
                unsigned bfr[4];
                ldsm4(bfr, ssb + j * 1152 + qp * 64);
                mma16816(d[j], fa[2 * qp],     bfr[0], bfr[1]);
                mma16816(d[j], fa[2 * qp + 1], bfr[2], bfr[3]);
                mma16816(d[j], fa[4 + 2 * qp],     bfr[0], bfr[1]);
                mma16816(d[j], fa[4 + 2 * qp + 1], bfr[2], bfr[3]);
            }
        }

        // ---- epilogue: w = rn_bf16(exp(pot)); Z from rounded values ----
        unsigned wh[4][4];
        #pragma unroll
        for (int j = 0; j < 8; j++) {
            float e0 = __expf(d[j][0]);
            float e1 = __expf(d[j][1]);
            float e2 = __expf(d[j][2]);
            float e3 = __expf(d[j][3]);
            const int q = j >> 1, bx = (j & 1) * 2;
            unsigned p01 = packrn(e0, e1);
            unsigned p23 = packrn(e2, e3);
            wh[q][bx]     = p01;
            wh[q][bx + 1] = p23;
            zacc0 += __uint_as_float(p01 << 16) +
                     __uint_as_float(p01 & 0xFFFF0000u);
            zacc1 += __uint_as_float(p23 << 16) +
                     __uint_as_float(p23 & 0xFFFF0000u);
        }

        // ---- GEMM2: M[16 rows][64 i] += w . S (B via ldmatrix.trans) ----
        #pragma unroll
        for (int j = 0; j < 8; j++) {
            #pragma unroll
            for (int qp = 0; qp < 2; qp++) {
                unsigned bfr[4];
                ldsm4t(bfr, sst + qp * 4608 + j * 16);
                mma16816(macc[j], wh[2 * qp],     bfr[0], bfr[1]);
                mma16816(macc[j], wh[2 * qp + 1], bfr[2], bfr[3]);
            }
        }
    }
    #undef ISSUE

    // ---- Z partials (quad reduce) ----
    zacc0 += __shfl_xor_sync(0xFFFFFFFFu, zacc0, 1);
    zacc0 += __shfl_xor_sync(0xFFFFFFFFu, zacc0, 2);
    zacc1 += __shfl_xor_sync(0xFFFFFFFFu, zacc1, 1);
    zacc1 += __shfl_xor_sync(0xFFFFFFFFu, zacc1, 2);
    if ((lane & 3) == 0) {
        const int r = b0 + r0 + (lane >> 2);
        g_Zpart[blockIdx.x * NB + r]     = zacc0;
        g_Zpart[blockIdx.x * NB + r + 8] = zacc1;
    }

    // ---- M partials writeback ----
    {
        float* mb = g_Mpart + (size_t)blockIdx.x * (NB * NL)
                  + (size_t)(b0 + r0 + (lane >> 2)) * NL + (lane & 3) * 2;
        float* mb2 = mb + 8 * NL;
        #pragma unroll
        for (int j = 0; j < 8; j++) {
            *(float2*)(mb  + 8 * j) = make_float2(macc[j][0], macc[j][1]);
            *(float2*)(mb2 + 8 * j) = make_float2(macc[j][2], macc[j][3]);
        }
    }
}

// ------- finalize: LDG.128 split sums, pMargin, BCE, last-block loss -------
// grid 256 x 256 threads. Block owns 32 float4 columns (=128 idx).
// Thread (g, v): g=t>>5 sums splits k = g, g+8, ... for float4 column v.
__global__ void finalize_kernel(const float* __restrict__ y,
                                const float* __restrict__ mask,
                                float* __restrict__ out) {
    const int t   = threadIdx.x;
    const int blk = blockIdx.x;
    const int v   = t & 31;
    const int g   = t >> 5;
    const int vec = blk * 32 + v;          // global float4 column, 0..8191

    float4 acc = make_float4(0.f, 0.f, 0.f, 0.f);
    #pragma unroll
    for (int k = g; k < SPLITS; k += 8) {
        float4 q = ((const float4*)g_Mpart)[(size_t)k * 8192 + vec];
        acc.x += q.x; acc.y += q.y; acc.z += q.z; acc.w += q.w;
    }

    __shared__ float4 s4[8][32];
    __shared__ float Zsm[2];
    __shared__ float red[256];
    __shared__ int slast;

    // Z for the two b-rows this block covers (warps 2-3, strided + shfl)
    if (t >= 64 && t < 128) {
        const int bloc = (t >> 5) & 1;
        const int b    = blk * 2 + bloc;
        float z = 0.f;
        for (int k = t & 31; k < SPLITS; k += 32) z += g_Zpart[k * NB + b];
        #pragma unroll
        for (int o = 16; o > 0; o >>= 1) z += __shfl_xor_sync(0xFFFFFFFFu, z, o);
        if ((t & 31) == 0) Zsm[bloc] = z;
    }
    s4[g][v] = acc;
    __syncthreads();

    float bsum = 0.f;
    if (t < 32) {
        float4 m = s4[0][t];
        #pragma unroll
        for (int gg = 1; gg < 8; gg++) {
            float4 q = s4[gg][t];
            m.x += q.x; m.y += q.y; m.z += q.z; m.w += q.w;
        }
        const float Z = Zsm[t >> 4];
        const int idx = blk * 128 + t * 4;
        float p0 = m.x / Z, p1 = m.y / Z, p2 = m.z / Z, p3 = m.w / Z;
        out[1 + idx]     = p0;
        out[1 + idx + 1] = p1;
        out[1 + idx + 2] = p2;
        out[1 + idx + 3] = p3;

        float4 y4 = ((const float4*)y)[blk * 32 + t];
        float4 k4 = ((const float4*)mask)[blk * 32 + t];
        #define BCE(p, yv, mv)                                               \
            (-((yv) * fmaxf(logf(p), -100.f) +                               \
               (1.f - (yv)) * fmaxf(logf(fmaxf(1.f - (p), 0.f)), -100.f)) * (mv))
        bsum = BCE(p0, y4.x, k4.x) + BCE(p1, y4.y, k4.y)
             + BCE(p2, y4.z, k4.z) + BCE(p3, y4.w, k4.w);
        #undef BCE
        #pragma unroll
        for (int o = 16; o > 0; o >>= 1)
            bsum += __shfl_xor_sync(0xFFFFFFFFu, bsum, o);
    }

    // last-block final reduction (deterministic fixed-order sums)
    if (t == 0) {
        g_lpart[blk] = bsum;
        __threadfence();
        unsigned c = atomicAdd(&g_cnt, 1u);
        slast = (c == gridDim.x - 1) ? 1 : 0;
    }
    __syncthreads();
    if (slast) {
        red[t] = g_lpart[t];
        __syncthreads();
        #pragma unroll
        for (int off = 128; off > 0; off >>= 1) {
            if (t < off) red[t] += red[t + off];
            __syncthreads();
        }
        if (t == 0) {
            out[0] = red[0] * (1.f / NB);
            g_cnt = 0;                       // reset for next graph replay
        }
    }
}

extern "C" void kernel_launch(void* const* d_in, const int* in_sizes, int n_in,
                              void* d_out, int out_size) {
    const float* f    = (const float*)d_in[0];
    const float* S    = (const float*)d_in[1];
    const float* y    = (const float*)d_in[2];
    const float* mask = (const float*)d_in[3];
    float* out = (float*)d_out;

    conv_kernel<<<1024, 256>>>(S);
    dim3 grid(SPLITS, 4);
    main_kernel<<<grid, 256, SMEM_BYTES>>>(f);
    finalize_kernel<<<256, 256>>>(y, mask, out);
}

// round 9
// speedup vs baseline: 1.0077x; 1.0010x over previous
#include <cuda_runtime.h>

// ---------------------------------------------------------------------------
// pLoss, single fused persistent kernel (one wave: 296 CTAs = 2/SM x 148).
//   phase 0: all CTAs convert S (fp32 {0,1}) -> bf16 g_Sbf cooperatively
//   barrier1
//   phase 1: flash loop  pot = f.S^T (exact hi/lo bf16 split of f),
//            w = rn_bf16(exp(pot)) (Z sums the SAME rounded values),
//            M += w.S ; per-split slabs to g_Mpart/g_Zpart
//   barrier2
//   phase 2: CTAs 0..255: sum split slabs (LDG.128), pMargin -> out[1..],
//            BCE partials; all CTAs ack; last acker reduces loss -> out[0]
//            and resets all counters (safe: strictly after all spins exited).
// ---------------------------------------------------------------------------

#define NB       512
#define NL       64
#define SPLITS   74
#define CPS      7           // chunks per split (73*7 + 1 = 512)
#define TOTCH    512
#define NCTA     296

#define SSOF(b)  ((b) * 9216)      // 3 bf16 tile buffers, 64 rows x 144B
#define SMEM_BYTES 34816           // f staging (pre-loop) needs 128*272

__device__ unsigned short g_Sbf[32768 * 64];   // bf16 copy of S (4 MB)
__device__ float g_Zpart[SPLITS * NB];
__device__ __align__(16) float g_Mpart[SPLITS * NB * NL];
__device__ float g_lpart[256];
__device__ unsigned g_bar1, g_bar2, g_cnt;     // zero-init; self-resetting

// ---------------- helpers ----------------
__device__ __forceinline__ unsigned smem_u32(const void* p) {
    unsigned a;
    asm("{ .reg .u64 t; cvta.to.shared.u64 t, %1; cvt.u32.u64 %0, t; }"
        : "=r"(a) : "l"(p));
    return a;
}
__device__ __forceinline__ void ldsm4(unsigned* r, unsigned addr) {
    asm volatile("ldmatrix.sync.aligned.m8n8.x4.shared.b16 {%0,%1,%2,%3}, [%4];"
                 : "=r"(r[0]), "=r"(r[1]), "=r"(r[2]), "=r"(r[3]) : "r"(addr));
}
__device__ __forceinline__ void ldsm4t(unsigned* r, unsigned addr) {
    asm volatile("ldmatrix.sync.aligned.m8n8.x4.trans.shared.b16 {%0,%1,%2,%3}, [%4];"
                 : "=r"(r[0]), "=r"(r[1]), "=r"(r[2]), "=r"(r[3]) : "r"(addr));
}
__device__ __forceinline__ void mma16816(float* d, const unsigned* a,
                                         unsigned b0, unsigned b1) {
    asm volatile(
        "mma.sync.aligned.m16n8k16.row.col.f32.bf16.bf16.f32 "
        "{%0,%1,%2,%3}, {%4,%5,%6,%7}, {%8,%9}, {%0,%1,%2,%3};"
        : "+f"(d[0]), "+f"(d[1]), "+f"(d[2]), "+f"(d[3])
        : "r"(a[0]), "r"(a[1]), "r"(a[2]), "r"(a[3]), "r"(b0), "r"(b1));
}
__device__ __forceinline__ unsigned packhi(float a, float b) {   // exact trunc
    return __byte_perm(__float_as_uint(a), __float_as_uint(b), 0x7632);
}
__device__ __forceinline__ unsigned packlo(float a, float b) {   // exact residual
    float la = a - __uint_as_float(__float_as_uint(a) & 0xFFFF0000u);
    float lb = b - __uint_as_float(__float_as_uint(b) & 0xFFFF0000u);
    unsigned r;
    asm("cvt.rn.bf16x2.f32 %0, %1, %2;" : "=r"(r) : "f"(lb), "f"(la));
    return r;
}
__device__ __forceinline__ unsigned packrn(float a, float b) {   // rn round
    unsigned r;
    asm("cvt.rn.bf16x2.f32 %0, %1, %2;" : "=r"(r) : "f"(b), "f"(a));
    return r;
}
__device__ __forceinline__ void cpasync16(unsigned saddr, const void* g) {
    asm volatile("cp.async.cg.shared.global [%0], [%1], 16;"
                 :: "r"(saddr), "l"(g));
}
__device__ __forceinline__ void cp_commit() {
    asm volatile("cp.async.commit_group;" ::: "memory");
}
__device__ __forceinline__ void cp_wait1() {
    asm volatile("cp.async.wait_group 1;" ::: "memory");
}
// grid barrier: release-add, acquire-load spin. Safe: grid = one wave.
__device__ __forceinline__ void grid_sync(unsigned* ctr) {
    __syncthreads();
    if (threadIdx.x == 0) {
        __threadfence();                       // release our prior stores
        atomicAdd(ctr, 1u);
        unsigned v;
        do {
            asm volatile("ld.acquire.gpu.global.u32 %0, [%1];"
                         : "=r"(v) : "l"(ctr));
        } while (v < NCTA);
    }
    __syncthreads();
}

// ---------------- fused kernel ----------------
__global__ __launch_bounds__(256, 2)
void fused_kernel(const float* __restrict__ f, const float* __restrict__ Sg,
                  const float* __restrict__ y, const float* __restrict__ mask,
                  float* __restrict__ out) {
    extern __shared__ char smem[];
    const unsigned sb = smem_u32(smem);

    const int tid  = threadIdx.x;
    const int wid  = tid >> 5;
    const int lane = tid & 31;
    const int b0   = blockIdx.y * 128;
    const int c0   = blockIdx.x * CPS;
    const int c1   = min(c0 + CPS, TOTCH);
    const int cid  = blockIdx.y * SPLITS + blockIdx.x;   // 0..295

    // ================= phase 0: S -> bf16 (cooperative) =================
    {
        // 262144 uint4 outputs total; 886 per CTA (contiguous), strided by 256.
        const int base = cid * 886;
        #pragma unroll
        for (int k = 0; k < 4; k++) {
            int u = base + k * 256 + tid;
            if (u < base + 886 && u < 262144) {
                float4 a = ((const float4*)Sg)[2 * u];
                float4 b = ((const float4*)Sg)[2 * u + 1];
                uint4 o;
                o.x = packrn(a.x, a.y);  o.y = packrn(a.z, a.w);
                o.z = packrn(b.x, b.y);  o.w = packrn(b.z, b.w);
                ((uint4*)g_Sbf)[u] = o;
            }
        }
    }

    // ---- stage f hi/lo split into SMEM (local; no barrier needed yet) ----
    {
        const int b = tid >> 1, half = tid & 1;
        const float* fr = f + (size_t)(b0 + b) * NL + half * 32;
        char* frow = smem + b * 272;
        #pragma unroll
        for (int j = 0; j < 8; j++) {
            float4 v = *(const float4*)(fr + 4 * j);
            int ch = half * 32 + 4 * j;
            *(uint2*)(frow + ch * 2) =
                make_uint2(packhi(v.x, v.y), packhi(v.z, v.w));
            *(uint2*)(frow + (64 + ch) * 2) =
                make_uint2(packlo(v.x, v.y), packlo(v.z, v.w));
        }
    }
    __syncthreads();

    // ---- A fragments (f hi: q=0..3, f lo: q=4..7), persistent ----
    unsigned fa[8][4];
    const int r0 = wid * 16;
    {
        const unsigned laneA = (lane % 16) * 272 + (lane >> 4) * 16;
        #pragma unroll
        for (int q = 0; q < 8; q++)
            ldsm4(fa[q], sb + r0 * 272 + q * 32 + laneA);
    }

    grid_sync(&g_bar1);    // g_Sbf complete; f staging dead

    // ================= phase 1: flash loop =================
    const int q0 = tid, q1 = tid + 256;
    const unsigned so0 = (unsigned)((q0 >> 3) * 144 + (q0 & 7) * 16);
    const unsigned so1 = (unsigned)((q1 >> 3) * 144 + (q1 & 7) * 16);

    #define ISSUE(c, buf)                                                   \
        do {                                                                \
            const char* gb_ = (const char*)g_Sbf + (size_t)(c) * 8192;      \
            cpasync16(sb + SSOF(buf) + so0, gb_ + q0 * 16);                 \
            cpasync16(sb + SSOF(buf) + so1, gb_ + q1 * 16);                 \
        } while (0)

    ISSUE(c0, 0); cp_commit();
    if (c0 + 1 < c1) ISSUE(c0 + 1, 1);
    cp_commit();

    float macc[8][4];
    #pragma unroll
    for (int j = 0; j < 8; j++)
        #pragma unroll
        for (int k = 0; k < 4; k++) macc[j][k] = 0.f;
    float zacc0 = 0.f, zacc1 = 0.f;

    const unsigned laneB = (lane & 7) * 144 + (lane >> 3) * 16;  // GEMM1
    const unsigned laneT = lane * 144;                           // GEMM2 (trans)

    for (int c = c0; c < c1; c++) {
        const int idx = c - c0;
        const int buf = idx % 3;

        cp_wait1();
        __syncthreads();

        if (c + 2 < c1) ISSUE(c + 2, (idx + 2) % 3);
        cp_commit();

        const unsigned ssb = sb + SSOF(buf) + laneB;
        const unsigned sst = sb + SSOF(buf) + laneT;

        // GEMM1: scores[16 rows][64 s] = f . S^T
        float d[8][4];
        #pragma unroll
        for (int j = 0; j < 8; j++)
            #pragma unroll
            for (int k = 0; k < 4; k++) d[j][k] = 0.f;

        #pragma unroll
        for (int j = 0; j < 8; j++) {
            #pragma unroll
            for (int qp = 0; qp < 2; qp++) {
                unsigned bfr[4];
                ldsm4(bfr, ssb + j * 1152 + qp * 64);
                mma16816(d[j], fa[2 * qp],     bfr[0], bfr[1]);
                mma16816(d[j], fa[2 * qp + 1], bfr[2], bfr[3]);
                mma16816(d[j], fa[4 + 2 * qp],     bfr[0], bfr[1]);
                mma16816(d[j], fa[4 + 2 * qp + 1], bfr[2], bfr[3]);
            }
        }

        // epilogue: w = rn_bf16(exp(pot)); Z from the rounded values
        unsigned wh[4][4];
        #pragma unroll
        for (int j = 0; j < 8; j++) {
            float e0 = __expf(d[j][0]);
            float e1 = __expf(d[j][1]);
            float e2 = __expf(d[j][2]);
            float e3 = __expf(d[j][3]);
            const int q = j >> 1, bx = (j & 1) * 2;
            unsigned p01 = packrn(e0, e1);
            unsigned p23 = packrn(e2, e3);
            wh[q][bx]     = p01;
            wh[q][bx + 1] = p23;
            zacc0 += __uint_as_float(p01 << 16) +
                     __uint_as_float(p01 & 0xFFFF0000u);
            zacc1 += __uint_as_float(p23 << 16) +
                     __uint_as_float(p23 & 0xFFFF0000u);
        }

        // GEMM2: M[16 rows][64 i] += w . S (B via ldmatrix.trans)
        #pragma unroll
        for (int j = 0; j < 8; j++) {
            #pragma unroll
            for (int qp = 0; qp < 2; qp++) {
                unsigned bfr[4];
                ldsm4t(bfr, sst + qp * 4608 + j * 16);
                mma16816(macc[j], wh[2 * qp],     bfr[0], bfr[1]);
                mma16816(macc[j], wh[2 * qp + 1], bfr[2], bfr[3]);
            }
        }
    }
    #undef ISSUE

    // Z partials (quad reduce)
    zacc0 += __shfl_xor_sync(0xFFFFFFFFu, zacc0, 1);
    zacc0 += __shfl_xor_sync(0xFFFFFFFFu, zacc0, 2);
    zacc1 += __shfl_xor_sync(0xFFFFFFFFu, zacc1, 1);
    zacc1 += __shfl_xor_sync(0xFFFFFFFFu, zacc1, 2);
    if ((lane & 3) == 0) {
        const int r = b0 + r0 + (lane >> 2);
        g_Zpart[blockIdx.x * NB + r]     = zacc0;
        g_Zpart[blockIdx.x * NB + r + 8] = zacc1;
    }

    // M partials writeback
    {
        float* mb = g_Mpart + (size_t)blockIdx.x * (NB * NL)
                  + (size_t)(b0 + r0 + (lane >> 2)) * NL + (lane & 3) * 2;
        float* mb2 = mb + 8 * NL;
        #pragma unroll
        for (int j = 0; j < 8; j++) {
            *(float2*)(mb  + 8 * j) = make_float2(macc[j][0], macc[j][1]);
            *(float2*)(mb2 + 8 * j) = make_float2(macc[j][2], macc[j][3]);
        }
    }

    grid_sync(&g_bar2);    // all M/Z slabs visible

    // ================= phase 2: finalize (CTAs 0..255) =================
    __shared__ float4 s4[8][32];
    __shared__ float Zsm[2];
    __shared__ float red[256];
    __shared__ int slast;

    float bsum = 0.f;
    if (cid < 256) {
        const int v = tid & 31;
        const int g = tid >> 5;
        const int vec = cid * 32 + v;          // global float4 column

        float4 acc = make_float4(0.f, 0.f, 0.f, 0.f);
        #pragma unroll
        for (int k = g; k < SPLITS; k += 8) {
            float4 q = ((const float4*)g_Mpart)[(size_t)k * 8192 + vec];
            acc.x += q.x; acc.y += q.y; acc.z += q.z; acc.w += q.w;
        }

        if (tid >= 64 && tid < 128) {          // Z for this block's two b-rows
            const int bloc = (tid >> 5) & 1;
            const int b    = cid * 2 + bloc;
            float z = 0.f;
            for (int k = tid & 31; k < SPLITS; k += 32)
                z += g_Zpart[k * NB + b];
            #pragma unroll
            for (int o = 16; o > 0; o >>= 1)
                z += __shfl_xor_sync(0xFFFFFFFFu, z, o);
            if ((tid & 31) == 0) Zsm[bloc] = z;
        }
        s4[g][v] = acc;
        __syncthreads();

        if (tid < 32) {
            float4 m = s4[0][tid];
            #pragma unroll
            for (int gg = 1; gg < 8; gg++) {
                float4 q = s4[gg][tid];
                m.x += q.x; m.y += q.y; m.z += q.z; m.w += q.w;
            }
            const float Z = Zsm[tid >> 4];
            const int idx = cid * 128 + tid * 4;
            float p0 = m.x / Z, p1 = m.y / Z, p2 = m.z / Z, p3 = m.w / Z;
            out[1 + idx]     = p0;
            out[1 + idx + 1] = p1;
            out[1 + idx + 2] = p2;
            out[1 + idx + 3] = p3;

            float4 y4 = ((const float4*)y)[cid * 32 + tid];
            float4 k4 = ((const float4*)mask)[cid * 32 + tid];
            #define BCE(p, yv, mv)                                           \
                (-((yv) * fmaxf(logf(p), -100.f) +                           \
                   (1.f - (yv)) * fmaxf(logf(fmaxf(1.f - (p), 0.f)),         \
                                        -100.f)) * (mv))
            bsum = BCE(p0, y4.x, k4.x) + BCE(p1, y4.y, k4.y)
                 + BCE(p2, y4.z, k4.z) + BCE(p3, y4.w, k4.w);
            #undef BCE
            #pragma unroll
            for (int o = 16; o > 0; o >>= 1)
                bsum += __shfl_xor_sync(0xFFFFFFFFu, bsum, o);
            if (tid == 0) g_lpart[cid] = bsum;
        }
    }
    __syncthreads();

    // ---- ack; last acker reduces loss and resets counters ----
    if (tid == 0) {
        __threadfence();
        unsigned c = atomicAdd(&g_cnt, 1u);
        slast = (c == NCTA - 1) ? 1 : 0;
    }
    __syncthreads();
    if (slast) {
        __threadfence();                       // acquire all g_lpart writes
        red[tid] = (tid < 256) ? g_lpart[tid] : 0.f;
        __syncthreads();
        #pragma unroll
        for (int off = 128; off > 0; off >>= 1) {
            if (tid < off) red[tid] += red[tid + off];
            __syncthreads();
        }
        if (tid == 0) {
            out[0] = red[0] * (1.f / NB);
            g_bar1 = 0; g_bar2 = 0; g_cnt = 0;   // strictly after all spins
        }
    }
}

extern "C" void kernel_launch(void* const* d_in, const int* in_sizes, int n_in,
                              void* d_out, int out_size) {
    const float* f    = (const float*)d_in[0];
    const float* S    = (const float*)d_in[1];
    const float* y    = (const float*)d_in[2];
    const float* mask = (const float*)d_in[3];
    float* out = (float*)d_out;

    dim3 grid(SPLITS, 4);
    fused_kernel<<<grid, 256, SMEM_BYTES>>>(f, S, y, mask, out);
}